// round 12
// baseline (speedup 1.0000x reference)
#include <cuda_runtime.h>
#include <cstdint>

#define EMB_DIM  1024
#define LN_EPS   1e-5f
#define MAX_B    8192
#define MAX_R    5120      // prepass supports up to 5120 relations
#define T_STAGED 696       // T rows staged in smem (of 1024); rest read via L2

// ---------------- device scratch (no allocation allowed) ----------------
__device__ int g_offs[MAX_R + 1];   // per-relation exclusive offsets
__device__ int g_rows[MAX_B];       // batch indices grouped by relation

// ---------------- prepass: ONE single-block kernel ----------------
// sniff (512 words) -> ids to u16 smem (single gmem pass) -> hist/scan/scatter in smem.
__global__ __launch_bounds__(1024)
void prepass_kernel(const int* __restrict__ w, int n_ids, int batch, int R) {
    __shared__ int hist[MAX_R];              // counts, then scatter cursors (20.5 KB)
    __shared__ unsigned short sid[MAX_B];    // ids cached in smem (16 KB)
    __shared__ int wsum[32];
    const int t = threadIdx.x, lid = t & 31, wid = t >> 5;

    // dtype sniff on first <=512 words: odd words all zero <=> int64 (values < 5000)
    const int lim = (n_ids < 512) ? n_ids : 512;
    int nz = 0;
    for (int i = 1 + 2 * t; i < lim; i += 2048) nz |= (w[i] != 0);
    const int is64 = (__syncthreads_or(nz) == 0);

    for (int i = t; i < R; i += 1024) hist[i] = 0;
    __syncthreads();

    // single coalesced pass over ids: cache in smem + histogram
    for (int b = t; b < batch; b += 1024) {
        const int id = is64 ? w[2 * b] : w[b];
        sid[b] = (unsigned short)id;
        atomicAdd(&hist[id], 1);
    }
    __syncthreads();

    // exclusive scan of hist: 5 elems/thread, warp-shuffle based
    const int base = t * 5;
    int loc[5];
    int s = 0;
#pragma unroll
    for (int i = 0; i < 5; ++i) {
        const int v = (base + i < R) ? hist[base + i] : 0;
        loc[i] = v; s += v;
    }
    int ss = s;
#pragma unroll
    for (int o = 1; o < 32; o <<= 1) {
        const int v = __shfl_up_sync(~0u, ss, o);
        if (lid >= o) ss += v;
    }
    if (lid == 31) wsum[wid] = ss;
    __syncthreads();
    if (t < 32) {
        const int v = wsum[t];
        int vv = v;
#pragma unroll
        for (int o = 1; o < 32; o <<= 1) {
            const int u = __shfl_up_sync(~0u, vv, o);
            if (t >= o) vv += u;
        }
        wsum[t] = vv - v;                    // exclusive warp offset
    }
    __syncthreads();
    const int excl = wsum[wid] + (ss - s);   // thread's exclusive prefix
    int run = excl;
#pragma unroll
    for (int i = 0; i < 5; ++i) {
        if (base + i < R) { g_offs[base + i] = run; run += loc[i]; }
    }
    if (t == 1023) g_offs[R] = run;

    // rebuild hist as scatter cursors (each thread touches only its own chunk)
    {
        int r2 = excl;
#pragma unroll
        for (int i = 0; i < 5; ++i) {
            if (base + i < R) { hist[base + i] = r2; r2 += loc[i]; }
        }
    }
    __syncthreads();

    // counting-sort scatter from smem ids
    for (int b = t; b < batch; b += 1024) {
        const int pos = atomicAdd(&hist[sid[b]], 1);
        g_rows[pos] = b;
    }
}

// ---------------- main: ONE CTA per relation, LayerNorm inline ----------------
// Stages T rows [0, T_STAGED) (44.5 KB) once; rows >= T_STAGED are read from
// gmem per batch row (DRAM once, L2 on repeats). Full 1024-row output per CTA
// -> stats computed locally, normalized and written exactly once.
__global__ __launch_bounds__(256)
void wproj_full_kernel(
    const float* __restrict__ ent_emb,   // [B, 1024]
    const float* __restrict__ tran,      // [R, 1024, 16]
    const float* __restrict__ bias,      // [R, 1024]
    const float* __restrict__ ln_w,
    const float* __restrict__ ln_b,
    float*       __restrict__ out)       // [B, 1024]
{
    const int rel   = blockIdx.x;
    const int start = g_offs[rel];
    const int end   = g_offs[rel + 1];
    if (start >= end) return;

    __shared__ float4 Ts4[T_STAGED * 4];   // 44544 B
    __shared__ float4 Es4[256];            // 4 KB entity row
    __shared__ float  rs[8], rs2[8];

    const int t   = threadIdx.x;
    const int q   = t & 3;                 // quad lane
    const int rr  = t >> 2;                // base row (0..63)
    const int wid = t >> 5, lid = t & 31;

    const float4* Tg = reinterpret_cast<const float4*>(tran) + (size_t)rel * 4096;
    const float*  Bg = bias + (size_t)rel * EMB_DIM;

    // bias in registers (quad-redundant loads hit the same cache lines)
    float breg[16];
#pragma unroll
    for (int j = 0; j < 16; ++j) breg[j] = __ldg(Bg + rr + 64 * j);

    // stage first T_STAGED rows (streaming: each byte used only via smem after this)
    for (int i = t; i < T_STAGED * 4; i += 256)
        Ts4[i] = __ldcs(Tg + i);

    // prefetch first entity row
    int b = g_rows[start];
    float4 epref = __ldg(reinterpret_cast<const float4*>(ent_emb) + (size_t)b * 256 + t);

    for (int row = start; row < end; ++row) {
        __syncthreads();                   // prior-iter Es/rs reads done
        Es4[t] = epref;
        __syncthreads();                   // Es visible (and Ts, first iter)

        const int bn = (row + 1 < end) ? g_rows[row + 1] : b;
        if (row + 1 < end)
            epref = __ldg(reinterpret_cast<const float4*>(ent_emb) + (size_t)bn * 256 + t);

        float x[16];
        float s = 0.f, s2 = 0.f;
#pragma unroll
        for (int j = 0; j < 16; ++j) {
            const int r = rr + 64 * j;                 // output row 0..1023
            const float4 tv = (r < T_STAGED) ? Ts4[r * 4 + q]
                                             : __ldg(Tg + r * 4 + q);   // L2 on repeats
            const float4 ev = Es4[(r >> 4) * 4 + q];
            float acc = tv.x * ev.x + tv.y * ev.y + tv.z * ev.z + tv.w * ev.w;
            acc += __shfl_xor_sync(0xffffffffu, acc, 1);   // quad sum -> 16-wide dot
            acc += __shfl_xor_sync(0xffffffffu, acc, 2);
            acc += breg[j];
            x[j] = acc;
            s += acc; s2 += acc * acc;                 // each row counted 4x
        }

        // block reduction (denominator 4 * 1024)
#pragma unroll
        for (int o = 16; o > 0; o >>= 1) {
            s  += __shfl_xor_sync(0xffffffffu, s,  o);
            s2 += __shfl_xor_sync(0xffffffffu, s2, o);
        }
        if (lid == 0) { rs[wid] = s; rs2[wid] = s2; }
        __syncthreads();
        float S = 0.f, S2 = 0.f;                       // every thread sums 8 (broadcast)
#pragma unroll
        for (int i = 0; i < 8; ++i) { S += rs[i]; S2 += rs2[i]; }

        const float mean = S  * (1.0f / 4096.0f);
        const float var  = S2 * (1.0f / 4096.0f) - mean * mean;
        const float rstd = rsqrtf(var + LN_EPS);

        float* ob = out + (size_t)b * EMB_DIM;
#pragma unroll
        for (int j = 0; j < 16; ++j) {
            if ((j & 3) == q) {                        // one writer/row; 8 consecutive floats/warp
                const int r = rr + 64 * j;
                ob[r] = (x[j] - mean) * rstd * __ldg(ln_w + r) + __ldg(ln_b + r);
            }
        }
        b = bn;
    }
}

// ---------------- launch ----------------
extern "C" void kernel_launch(void* const* d_in, const int* in_sizes, int n_in,
                              void* d_out, int out_size) {
    const float* ent_emb = (const float*)d_in[0];
    const void*  ids     = d_in[1];
    const float* tran    = (const float*)d_in[2];
    const float* bias    = (const float*)d_in[3];
    const float* ln_w    = (const float*)d_in[4];
    const float* ln_b    = (const float*)d_in[5];
    float*       out     = (float*)d_out;

    const int batch = in_sizes[0] / EMB_DIM;               // 8192
    const int R     = in_sizes[2] / (EMB_DIM * 16);        // 5000
    const int n_ids = in_sizes[1];

    prepass_kernel<<<1, 1024>>>((const int*)ids, n_ids, batch, R);
    wproj_full_kernel<<<R, 256>>>(ent_emb, tran, bias, ln_w, ln_b, out);
}

// round 13
// speedup vs baseline: 2.1621x; 2.1621x over previous
#include <cuda_runtime.h>
#include <cstdint>

#define EMB_DIM  1024
#define LN_EPS   1e-5f

// Flag: 1 if proj_ids buffer is int64, 0 if int32.
__device__ int g_ids_is64;

// dtype sniff on first <=512 words only: for int64 (little-endian, ids < 5000)
// every odd 32-bit word is zero. For int32, odd words are random ids —
// P(all zero) ~ (1/5000)^256. In-bounds under both interpretations.
__global__ void detect_ids_dtype_kernel(const int* __restrict__ w, int n_ids) {
    const int lim = (n_ids < 512) ? n_ids : 512;
    int nz = 0;
    for (int i = 1 + 2 * threadIdx.x; i < lim; i += 512) nz |= (w[i] != 0);
    if (__syncthreads_or(nz) == 0) {
        if (threadIdx.x == 0) g_ids_is64 = 1;
    } else {
        if (threadIdx.x == 0) g_ids_is64 = 0;
    }
}

// One CTA (256 threads) per batch row.
// Quad layout: lanes q = t&3 cooperate on each T row -> every warp LDG.128
// covers 512B contiguous (4 wavefronts, fully coalesced), fixing R1's 4x
// L1-wavefront amplification. Pre-norm x lives in smem, not registers.
__global__ __launch_bounds__(256)
void wproj_ln_kernel(
    const float* __restrict__ ent_emb,   // [B, 1024]
    const void*  __restrict__ proj_ids,  // [B] int32 or int64
    const float* __restrict__ tran,      // [R, 1024, 16]
    const float* __restrict__ bias,      // [R, 1024]
    const float* __restrict__ ln_w,      // [1024]
    const float* __restrict__ ln_b,      // [1024]
    float*       __restrict__ out)       // [B, 1024]
{
    const int b = blockIdx.x;
    const int t = threadIdx.x;

    __shared__ float4 Es4[EMB_DIM / 4];  // 4 KB entity row
    __shared__ float  Xs[EMB_DIM];       // 4 KB pre-norm values
    __shared__ float  rs[8], rs2[8];

    // stage entity row (coalesced float4)
    Es4[t] = reinterpret_cast<const float4*>(ent_emb + (size_t)b * EMB_DIM)[t];
    __syncthreads();

    long long rel;
    if (g_ids_is64) rel = reinterpret_cast<const long long*>(proj_ids)[b];
    else            rel = (long long)reinterpret_cast<const int*>(proj_ids)[b];

    const float4* Tg4 = reinterpret_cast<const float4*>(tran) + (size_t)rel * 4096;
    const float*  Bb  = bias + (size_t)rel * EMB_DIM;

    const int q  = t & 3;    // quad lane: k-chunk [4q, 4q+4)
    const int rr = t >> 2;   // base row (0..63)

    float s = 0.f, s2 = 0.f;
#pragma unroll
    for (int j = 0; j < 16; ++j) {
        const int r = rr + 64 * j;                    // output row 0..1023
        const float4 tv = __ldg(Tg4 + r * 4 + q);     // warp: 512B contiguous
        const float4 ev = Es4[(r >> 4) * 4 + q];      // 8 distinct float4/warp, multicast
        float acc = tv.x * ev.x + tv.y * ev.y + tv.z * ev.z + tv.w * ev.w;
        acc += __shfl_xor_sync(0xffffffffu, acc, 1);  // quad sum -> full 16-wide dot
        acc += __shfl_xor_sync(0xffffffffu, acc, 2);
        acc += __ldg(Bb + r);
        if (q == 0) Xs[r] = acc;                      // 8 writers/warp, distinct banks
        s  += acc;                                    // each row counted 4x
        s2 += acc * acc;
    }

    // block reduction (denominator 4 * 1024)
#pragma unroll
    for (int o = 16; o > 0; o >>= 1) {
        s  += __shfl_xor_sync(0xffffffffu, s,  o);
        s2 += __shfl_xor_sync(0xffffffffu, s2, o);
    }
    const int wid = t >> 5, lid = t & 31;
    if (lid == 0) { rs[wid] = s; rs2[wid] = s2; }
    __syncthreads();                                  // also fences Xs writes

    float S = 0.f, S2 = 0.f;                          // every thread sums 8 partials
#pragma unroll
    for (int i = 0; i < 8; ++i) { S += rs[i]; S2 += rs2[i]; }

    const float mean = S  * (1.0f / 4096.0f);
    const float var  = S2 * (1.0f / 4096.0f) - mean * mean;
    const float rstd = rsqrtf(var + LN_EPS);

    // normalize + write: one float4 per thread, fully coalesced
    const float4 xv = reinterpret_cast<const float4*>(Xs)[t];
    const float4 w  = __ldg(reinterpret_cast<const float4*>(ln_w) + t);
    const float4 c  = __ldg(reinterpret_cast<const float4*>(ln_b) + t);
    float4 o;
    o.x = (xv.x - mean) * rstd * w.x + c.x;
    o.y = (xv.y - mean) * rstd * w.y + c.y;
    o.z = (xv.z - mean) * rstd * w.z + c.z;
    o.w = (xv.w - mean) * rstd * w.w + c.w;
    reinterpret_cast<float4*>(out + (size_t)b * EMB_DIM)[t] = o;
}

extern "C" void kernel_launch(void* const* d_in, const int* in_sizes, int n_in,
                              void* d_out, int out_size) {
    const float* ent_emb = (const float*)d_in[0];
    const void*  ids     = d_in[1];
    const float* tran    = (const float*)d_in[2];
    const float* bias    = (const float*)d_in[3];
    const float* ln_w    = (const float*)d_in[4];
    const float* ln_b    = (const float*)d_in[5];
    float*       out     = (float*)d_out;

    const int batch = in_sizes[0] / EMB_DIM;   // 8192
    const int n_ids = in_sizes[1];

    detect_ids_dtype_kernel<<<1, 256>>>((const int*)ids, n_ids);
    wproj_ln_kernel<<<batch, 256>>>(ent_emb, ids, tran, bias, ln_w, ln_b, out);
}

// round 14
// speedup vs baseline: 2.4480x; 1.1322x over previous
#include <cuda_runtime.h>
#include <cstdint>

#define EMB_DIM  1024
#define LN_EPS   1e-5f
#define MAX_B    8192
#define MAX_R    5120      // prepass supports up to 5120 relations

// ---------------- device scratch (no allocation allowed) ----------------
__device__ int g_ids_is64;
__device__ int g_rows[MAX_B];       // batch indices grouped (sorted) by relation

// ---------------- prepass: ONE single-block kernel (validated R12) --------
// sniff (<=512 words) -> ids to u16 smem (single gmem pass) -> hist/scan/scatter.
__global__ __launch_bounds__(1024)
void prepass_kernel(const int* __restrict__ w, int n_ids, int batch, int R) {
    __shared__ int hist[MAX_R];              // counts, then scatter cursors
    __shared__ unsigned short sid[MAX_B];    // ids cached in smem
    __shared__ int wsum[32];
    const int t = threadIdx.x, lid = t & 31, wid = t >> 5;

    // dtype sniff: odd words of first <=512 words all zero <=> int64 (ids < 5000)
    const int lim = (n_ids < 512) ? n_ids : 512;
    int nz = 0;
    for (int i = 1 + 2 * t; i < lim; i += 2048) nz |= (w[i] != 0);
    const int is64 = (__syncthreads_or(nz) == 0);
    if (t == 0) g_ids_is64 = is64;

    for (int i = t; i < R; i += 1024) hist[i] = 0;
    __syncthreads();

    // single coalesced pass over ids: cache + histogram
    for (int b = t; b < batch; b += 1024) {
        const int id = is64 ? w[2 * b] : w[b];
        sid[b] = (unsigned short)id;
        atomicAdd(&hist[id], 1);
    }
    __syncthreads();

    // exclusive scan of hist: 5 elems/thread, warp-shuffle based
    const int base = t * 5;
    int loc[5];
    int s = 0;
#pragma unroll
    for (int i = 0; i < 5; ++i) {
        const int v = (base + i < R) ? hist[base + i] : 0;
        loc[i] = v; s += v;
    }
    int ss = s;
#pragma unroll
    for (int o = 1; o < 32; o <<= 1) {
        const int v = __shfl_up_sync(~0u, ss, o);
        if (lid >= o) ss += v;
    }
    if (lid == 31) wsum[wid] = ss;
    __syncthreads();
    if (t < 32) {
        const int v = wsum[t];
        int vv = v;
#pragma unroll
        for (int o = 1; o < 32; o <<= 1) {
            const int u = __shfl_up_sync(~0u, vv, o);
            if (t >= o) vv += u;
        }
        wsum[t] = vv - v;                    // exclusive warp offset
    }
    __syncthreads();
    const int excl = wsum[wid] + (ss - s);   // thread's exclusive prefix

    // hist becomes scatter cursors (each thread touches only its own chunk)
    {
        int r2 = excl;
#pragma unroll
        for (int i = 0; i < 5; ++i) {
            if (base + i < R) { hist[base + i] = r2; r2 += loc[i]; }
        }
    }
    __syncthreads();

    // counting-sort scatter from smem ids
    for (int b = t; b < batch; b += 1024) {
        const int pos = atomicAdd(&hist[sid[b]], 1);
        g_rows[pos] = b;
    }
}

// ---------------- main: one CTA per batch row (sorted order) ----------------
// Quad-coalesced T loads (R13). Bias + LayerNorm stats DEFERRED out of the
// hot loop: the loop produces pure dots into Xs; the tail adds bias as
// float4, computes stats once per element (denominator 1024), normalizes.
__global__ __launch_bounds__(256)
void wproj_ln_kernel(
    const float* __restrict__ ent_emb,   // [B, 1024]
    const void*  __restrict__ proj_ids,  // [B] int32 or int64
    const float* __restrict__ tran,      // [R, 1024, 16]
    const float* __restrict__ bias,      // [R, 1024]
    const float* __restrict__ ln_w,      // [1024]
    const float* __restrict__ ln_b,      // [1024]
    float*       __restrict__ out)       // [B, 1024]
{
    const int b = g_rows[blockIdx.x];
    const int t = threadIdx.x;

    __shared__ float4 Es4[EMB_DIM / 4];  // 4 KB entity row
    __shared__ float  Xs[EMB_DIM];       // 4 KB pure-dot values
    __shared__ float  rs[8], rs2[8];

    // stage entity row (coalesced float4)
    Es4[t] = reinterpret_cast<const float4*>(ent_emb + (size_t)b * EMB_DIM)[t];
    __syncthreads();

    long long rel;
    if (g_ids_is64) rel = reinterpret_cast<const long long*>(proj_ids)[b];
    else            rel = (long long)reinterpret_cast<const int*>(proj_ids)[b];

    const float4* Tg4 = reinterpret_cast<const float4*>(tran) + (size_t)rel * 4096;
    const float4* Bb4 = reinterpret_cast<const float4*>(bias + (size_t)rel * EMB_DIM);

    const int q  = t & 3;    // quad lane: k-chunk [4q, 4q+4)
    const int rr = t >> 2;   // base row (0..63)

#pragma unroll
    for (int j = 0; j < 16; ++j) {
        const int r = rr + 64 * j;                    // output row 0..1023
        const float4 tv = __ldg(Tg4 + r * 4 + q);     // warp: 512B contiguous
        const float4 ev = Es4[(r >> 4) * 4 + q];      // broadcast, conflict-free
        float acc = tv.x * ev.x + tv.y * ev.y + tv.z * ev.z + tv.w * ev.w;
        acc += __shfl_xor_sync(0xffffffffu, acc, 1);  // quad sum -> full 16-wide dot
        acc += __shfl_xor_sync(0xffffffffu, acc, 2);
        if (q == 0) Xs[r] = acc;                      // 8 writers/warp, distinct banks
    }
    __syncthreads();                                  // Xs complete

    // tail: bias as float4, per-element stats (each element counted ONCE)
    const float4 dv = reinterpret_cast<const float4*>(Xs)[t];
    const float4 bv = __ldg(Bb4 + t);
    float4 x;
    x.x = dv.x + bv.x; x.y = dv.y + bv.y; x.z = dv.z + bv.z; x.w = dv.w + bv.w;

    float s  = x.x + x.y + x.z + x.w;
    float s2 = x.x * x.x + x.y * x.y + x.z * x.z + x.w * x.w;
#pragma unroll
    for (int o = 16; o > 0; o >>= 1) {
        s  += __shfl_xor_sync(0xffffffffu, s,  o);
        s2 += __shfl_xor_sync(0xffffffffu, s2, o);
    }
    const int wid = t >> 5, lid = t & 31;
    if (lid == 0) { rs[wid] = s; rs2[wid] = s2; }
    __syncthreads();

    float S = 0.f, S2 = 0.f;                          // every thread sums 8 partials
#pragma unroll
    for (int i = 0; i < 8; ++i) { S += rs[i]; S2 += rs2[i]; }

    const float mean = S  * (1.0f / 1024.0f);
    const float var  = S2 * (1.0f / 1024.0f) - mean * mean;
    const float rstd = rsqrtf(var + LN_EPS);

    const float4 w = __ldg(reinterpret_cast<const float4*>(ln_w) + t);
    const float4 c = __ldg(reinterpret_cast<const float4*>(ln_b) + t);
    float4 o;
    o.x = (x.x - mean) * rstd * w.x + c.x;
    o.y = (x.y - mean) * rstd * w.y + c.y;
    o.z = (x.z - mean) * rstd * w.z + c.z;
    o.w = (x.w - mean) * rstd * w.w + c.w;
    reinterpret_cast<float4*>(out + (size_t)b * EMB_DIM)[t] = o;
}

extern "C" void kernel_launch(void* const* d_in, const int* in_sizes, int n_in,
                              void* d_out, int out_size) {
    const float* ent_emb = (const float*)d_in[0];
    const void*  ids     = d_in[1];
    const float* tran    = (const float*)d_in[2];
    const float* bias    = (const float*)d_in[3];
    const float* ln_w    = (const float*)d_in[4];
    const float* ln_b    = (const float*)d_in[5];
    float*       out     = (float*)d_out;

    const int batch = in_sizes[0] / EMB_DIM;               // 8192
    const int R     = in_sizes[2] / (EMB_DIM * 16);        // 5000
    const int n_ids = in_sizes[1];

    prepass_kernel<<<1, 1024>>>((const int*)ids, n_ids, batch, R);
    wproj_ln_kernel<<<batch, 256>>>(ent_emb, ids, tran, bias, ln_w, ln_b, out);
}